// round 4
// baseline (speedup 1.0000x reference)
#include <cuda_runtime.h>
#include <cstdint>

// Output: [B=64, SRC_XLEN=16000, D=128] fp32.
// Rows r with (r % 4000) < 1000 get x[b, r % 4000, :]; all other rows zero.
//
// One-wave persistent kernel, 592 CTAs (148 SMs x 4):
//  - Each CTA zeroes a 37.5 KiB SMEM buffer ONCE, then thread 0 issues its
//    share of cp.async.bulk zero-stores back-to-back with NO intermediate
//    waits (buffer is constant zeros -> no reuse hazard). 384 MiB of zero
//    writes flow through the async proxy, bypassing L1tex.
//  - Concurrently, all 256 threads run a grid-stride copy loop: each x float4
//    is loaded once (L2-resident) and stored to its 4 segment destinations.

static constexpr int NCTA = 592;                 // 148 * 4 — exactly one wave
static constexpr int NTHR = 256;

static constexpr int CHUNK_ROWS = 75;
static constexpr int CHUNK_BYTES = CHUNK_ROWS * 512;        // 38400 B (37.5 KiB)
static constexpr int CHUNKS_PER_REGION = 3000 / CHUNK_ROWS; // 40
static constexpr int N_ZERO_CHUNKS = 256 * CHUNKS_PER_REGION; // 10240

static constexpr int TOTAL_F4 = 64 * 1000 * 32;             // 2,048,000 x float4
static constexpr int F4_PER_BATCH_IN = 1000 * 32;           // 32000
static constexpr int F4_PER_BATCH_OUT = 16000 * 32;         // 512000
static constexpr int F4_PER_SEG = 4000 * 32;                // 128000

__global__ __launch_bounds__(NTHR) void seg_zero_pad_kernel(
    const float4* __restrict__ x,   // [64, 1000, 32] float4
    float4* __restrict__ out        // [64, 16000, 32] float4
) {
    __shared__ __align__(128) float4 zbuf[CHUNK_BYTES / 16];

    const int bid = blockIdx.x;
    const int t = threadIdx.x;

    // ---- zero the staging buffer once (600 float4 / 256 threads) ----
    const float4 z = make_float4(0.f, 0.f, 0.f, 0.f);
    #pragma unroll
    for (int i = t; i < CHUNK_BYTES / 16; i += NTHR) zbuf[i] = z;
    __syncthreads();

    // ---- thread 0: fire-and-forget all zero bulk stores for this CTA ----
    if (t == 0) {
        unsigned saddr;
        asm("{ .reg .u64 tmp; cvta.to.shared.u64 tmp, %1; cvt.u32.u64 %0, tmp; }"
            : "=r"(saddr) : "l"(zbuf));
        asm volatile("fence.proxy.async.shared::cta;" ::: "memory");

        for (int c = bid; c < N_ZERO_CHUNKS; c += NCTA) {
            const int region = c / CHUNKS_PER_REGION;      // 0..255
            const int j = c - region * CHUNKS_PER_REGION;  // 0..39
            const int batch = region >> 2;
            const int seg = region & 3;
            const size_t dst_off = (size_t)batch * (16000u * 512u)
                                 + (size_t)(seg * 4000 + 1000) * 512u
                                 + (size_t)j * CHUNK_BYTES;
            unsigned long long gptr =
                (unsigned long long)__cvta_generic_to_global((char*)out + dst_off);
            asm volatile(
                "cp.async.bulk.global.shared::cta.bulk_group [%0], [%1], %2;"
                :: "l"(gptr), "r"(saddr), "r"((unsigned)CHUNK_BYTES) : "memory");
        }
        asm volatile("cp.async.bulk.commit_group;" ::: "memory");
    }

    // ---- all threads: grid-stride copy, 1 load -> 4 stores ----
    for (int i = bid * NTHR + t; i < TOTAL_F4; i += NCTA * NTHR) {
        const int batch = i / F4_PER_BATCH_IN;
        const int rem = i - batch * F4_PER_BATCH_IN;       // row*32 + d4, < 32000
        const float4 v = __ldg(&x[i]);
        const int base = batch * F4_PER_BATCH_OUT + rem;
        out[base] = v;
        out[base + F4_PER_SEG] = v;
        out[base + 2 * F4_PER_SEG] = v;
        out[base + 3 * F4_PER_SEG] = v;
    }

    // ---- drain pending bulk stores before exit ----
    if (t == 0) {
        asm volatile("cp.async.bulk.wait_group 0;" ::: "memory");
    }
}

extern "C" void kernel_launch(void* const* d_in, const int* in_sizes, int n_in,
                              void* d_out, int out_size) {
    const float4* x = (const float4*)d_in[0];
    float4* out = (float4*)d_out;
    seg_zero_pad_kernel<<<NCTA, NTHR>>>(x, out);
}

// round 6
// speedup vs baseline: 1.1033x; 1.1033x over previous
#include <cuda_runtime.h>
#include <cstdint>

// Output: [B=64, SRC_XLEN=16000, D=128] fp32.
// Rows r with (r % 4000) < 1000 get x[b, r % 4000, :]; all other rows zero.
//
// R3 structure (fine-grained interleaved zero/copy CTA stream) with the SMEM
// staging fill amortized 5x:
//  - Zero path: 2560 CTAs. Each fills a 30 KiB SMEM zero buffer ONCE, then
//    issues 5 contiguous cp.async.bulk stores (150 KiB contiguous zeros),
//    bypassing the L1tex store path for 384 MiB of output.
//  - Copy path: 8000 CTAs. Each thread: 1 LDG.128 of x, 4 STG.128 to the
//    four segment destinations (x read exactly once from DRAM).

static constexpr int B = 64;
static constexpr int SRC_XLEN = 16000;
static constexpr int L = 1000;
static constexpr int SEG_STRIDE = 4000;
static constexpr int D4 = 32;                   // float4 per row
static constexpr int ROW_BYTES = 512;

static constexpr int CHUNK_ROWS = 60;
static constexpr int CHUNK_BYTES = CHUNK_ROWS * ROW_BYTES;    // 30720 B
static constexpr int STORES_PER_CTA = 5;                      // 300 rows / CTA
static constexpr int CTAS_PER_REGION = 3000 / (CHUNK_ROWS * STORES_PER_CTA); // 10
static constexpr int N_ZERO_BLOCKS = B * 4 * CTAS_PER_REGION; // 2560
static constexpr int N_COPY_BLOCKS = (B * L * D4) / 256;      // 8000
static constexpr int N_BLOCKS = N_ZERO_BLOCKS + N_COPY_BLOCKS; // 10560
// 10560 = 320 * 33; interleave 25 copy : 8 zero per group of 33.

static constexpr int F4_PER_BATCH_OUT = SRC_XLEN * D4;        // 512000
static constexpr int F4_PER_SEG = SEG_STRIDE * D4;            // 128000

__global__ __launch_bounds__(256) void seg_zero_pad_kernel(
    const float4* __restrict__ x,   // [64, 1000, 32] float4
    float4* __restrict__ out        // [64, 16000, 32] float4
) {
    __shared__ __align__(128) float4 zbuf[CHUNK_BYTES / 16];

    const int bid = blockIdx.x;
    const int t = threadIdx.x;
    const int grp = bid / 33;
    const int lane = bid % 33;

    if (lane >= 25) {
        // ---------- zero block: fill SMEM once, 5 contiguous bulk stores ----------
        const int zid = grp * 8 + (lane - 25);            // 0 .. 2559
        const int region = zid / CTAS_PER_REGION;         // 0 .. 255
        const int j = zid - region * CTAS_PER_REGION;     // 0 .. 9
        const int batch = region >> 2;
        const int seg = region & 3;

        const size_t dst_base = (size_t)batch * SRC_XLEN * ROW_BYTES
                              + (size_t)(seg * SEG_STRIDE + L) * ROW_BYTES
                              + (size_t)j * (STORES_PER_CTA * CHUNK_BYTES);

        const float4 z = make_float4(0.f, 0.f, 0.f, 0.f);
        #pragma unroll
        for (int i = t; i < CHUNK_BYTES / 16; i += 256) zbuf[i] = z;
        __syncthreads();

        if (t == 0) {
            unsigned saddr;
            asm("{ .reg .u64 tmp; cvta.to.shared.u64 tmp, %1; cvt.u32.u64 %0, tmp; }"
                : "=r"(saddr) : "l"(zbuf));
            asm volatile("fence.proxy.async.shared::cta;" ::: "memory");
            #pragma unroll
            for (int s = 0; s < STORES_PER_CTA; s++) {
                unsigned long long gptr = (unsigned long long)
                    __cvta_generic_to_global((char*)out + dst_base
                                             + (size_t)s * CHUNK_BYTES);
                asm volatile(
                    "cp.async.bulk.global.shared::cta.bulk_group [%0], [%1], %2;"
                    :: "l"(gptr), "r"(saddr), "r"((unsigned)CHUNK_BYTES) : "memory");
            }
            asm volatile("cp.async.bulk.commit_group;" ::: "memory");
            asm volatile("cp.async.bulk.wait_group 0;" ::: "memory");
        }
    } else {
        // ---------- copy block: load x once, store to 4 segments ----------
        const int cid = grp * 25 + lane;                  // 0 .. 7999
        const int gtid = cid * 256 + t;                   // 0 .. 2,047,999
        const int batch = gtid / (L * D4);                // 0 .. 63
        const int r32 = gtid - batch * (L * D4);          // row*32 + d4, < 32000

        const float4 v = __ldg(&x[gtid]);
        float4* dst = out + (size_t)batch * F4_PER_BATCH_OUT + r32;
        dst[0] = v;
        dst[F4_PER_SEG] = v;
        dst[2 * F4_PER_SEG] = v;
        dst[3 * F4_PER_SEG] = v;
    }
}

extern "C" void kernel_launch(void* const* d_in, const int* in_sizes, int n_in,
                              void* d_out, int out_size) {
    const float4* x = (const float4*)d_in[0];
    float4* out = (float4*)d_out;
    seg_zero_pad_kernel<<<N_BLOCKS, 256>>>(x, out);
}

// round 8
// speedup vs baseline: 1.1480x; 1.0405x over previous
#include <cuda_runtime.h>
#include <cstdint>

// Output: [B=64, SRC_XLEN=16000, D=128] fp32.
// Rows r with (r % 4000) < 1000 get x[b, r % 4000, :]; all other rows zero.
//
// All 512 MiB of output writes flow through cp.async.bulk (async proxy),
// bypassing the L1tex per-thread store path entirely. Fine-grained CTAs
// (empirically the fastest structure: 1 bulk-store wait per zero CTA).
//  - Zero path: 12800 CTAs, each fills a 30 KiB SMEM zero buffer and issues
//    ONE bulk store (proven best granularity, R3).
//  - Copy path: 1600 CTAs, each stages a contiguous 20 KiB chunk of x into
//    SMEM (LDG->STS, x is read exactly once from DRAM / L2) and issues FOUR
//    bulk stores, one per segment destination.

static constexpr int B = 64;
static constexpr int SRC_XLEN = 16000;
static constexpr int L = 1000;
static constexpr int SEG_STRIDE = 4000;
static constexpr int D4 = 32;                    // float4 per row
static constexpr int ROW_BYTES = 512;

// zero path
static constexpr int ZCHUNK_ROWS = 60;
static constexpr int ZCHUNK_BYTES = ZCHUNK_ROWS * ROW_BYTES;      // 30720
static constexpr int ZCHUNKS_PER_REGION = 3000 / ZCHUNK_ROWS;     // 50
static constexpr int N_ZERO_BLOCKS = B * 4 * ZCHUNKS_PER_REGION;  // 12800

// copy path
static constexpr int CCHUNK_ROWS = 40;
static constexpr int CCHUNK_BYTES = CCHUNK_ROWS * ROW_BYTES;      // 20480
static constexpr int CCHUNK_F4 = CCHUNK_BYTES / 16;               // 1280
static constexpr int CCHUNKS_PER_BATCH = L / CCHUNK_ROWS;         // 25
static constexpr int N_COPY_BLOCKS = B * CCHUNKS_PER_BATCH;       // 1600

static constexpr int N_BLOCKS = N_ZERO_BLOCKS + N_COPY_BLOCKS;    // 14400
// 14400 = 1600 * 9; per group of 9: lane 0 = copy, lanes 1..8 = zero.

static constexpr int F4_PER_BATCH_IN = L * D4;                    // 32000
static constexpr size_t OUT_BATCH_BYTES = (size_t)SRC_XLEN * ROW_BYTES;   // 8,192,000
static constexpr size_t OUT_SEG_BYTES = (size_t)SEG_STRIDE * ROW_BYTES;   // 2,048,000

__global__ __launch_bounds__(256) void seg_zero_pad_kernel(
    const float4* __restrict__ x,   // [64, 1000, 32] float4
    float4* __restrict__ out        // [64, 16000, 32] float4
) {
    __shared__ __align__(128) float4 sbuf[ZCHUNK_BYTES / 16];   // 30 KiB

    const int bid = blockIdx.x;
    const int t = threadIdx.x;
    const int grp = bid / 9;
    const int lane = bid % 9;

    unsigned saddr;
    asm("{ .reg .u64 tmp; cvta.to.shared.u64 tmp, %1; cvt.u32.u64 %0, tmp; }"
        : "=r"(saddr) : "l"(sbuf));

    if (lane != 0) {
        // ------------- zero block: fill 30 KiB once, ONE bulk store -------------
        const int zid = grp * 8 + (lane - 1);             // 0 .. 12799
        const int region = zid / ZCHUNKS_PER_REGION;      // 0 .. 255
        const int j = zid - region * ZCHUNKS_PER_REGION;  // 0 .. 49
        const int batch = region >> 2;
        const int seg = region & 3;

        const size_t dst_off = (size_t)batch * OUT_BATCH_BYTES
                             + (size_t)seg * OUT_SEG_BYTES
                             + (size_t)L * ROW_BYTES
                             + (size_t)j * ZCHUNK_BYTES;

        const float4 z = make_float4(0.f, 0.f, 0.f, 0.f);
        #pragma unroll
        for (int i = t; i < ZCHUNK_BYTES / 16; i += 256) sbuf[i] = z;
        __syncthreads();

        if (t == 0) {
            asm volatile("fence.proxy.async.shared::cta;" ::: "memory");
            unsigned long long gptr =
                (unsigned long long)__cvta_generic_to_global((char*)out + dst_off);
            asm volatile(
                "cp.async.bulk.global.shared::cta.bulk_group [%0], [%1], %2;"
                :: "l"(gptr), "r"(saddr), "r"((unsigned)ZCHUNK_BYTES) : "memory");
            asm volatile("cp.async.bulk.commit_group;" ::: "memory");
            asm volatile("cp.async.bulk.wait_group 0;" ::: "memory");
        }
    } else {
        // ------------- copy block: stage 20 KiB of x, FOUR bulk stores -------------
        const int cid = grp;                              // 0 .. 1599
        const int batch = cid / CCHUNKS_PER_BATCH;        // 0 .. 63
        const int j = cid - batch * CCHUNKS_PER_BATCH;    // 0 .. 24

        const float4* xs = x + (size_t)batch * F4_PER_BATCH_IN + (size_t)j * CCHUNK_F4;
        #pragma unroll
        for (int k = 0; k < CCHUNK_F4 / 256; k++) {       // 5 iterations
            sbuf[t + k * 256] = __ldg(&xs[t + k * 256]);
        }
        __syncthreads();

        if (t == 0) {
            asm volatile("fence.proxy.async.shared::cta;" ::: "memory");
            const size_t base = (size_t)batch * OUT_BATCH_BYTES
                              + (size_t)j * CCHUNK_BYTES;
            #pragma unroll
            for (int s = 0; s < 4; s++) {
                unsigned long long gptr = (unsigned long long)
                    __cvta_generic_to_global((char*)out + base
                                             + (size_t)s * OUT_SEG_BYTES);
                asm volatile(
                    "cp.async.bulk.global.shared::cta.bulk_group [%0], [%1], %2;"
                    :: "l"(gptr), "r"(saddr), "r"((unsigned)CCHUNK_BYTES) : "memory");
            }
            asm volatile("cp.async.bulk.commit_group;" ::: "memory");
            asm volatile("cp.async.bulk.wait_group 0;" ::: "memory");
        }
    }
}

extern "C" void kernel_launch(void* const* d_in, const int* in_sizes, int n_in,
                              void* d_out, int out_size) {
    const float4* x = (const float4*)d_in[0];
    float4* out = (float4*)d_out;
    seg_zero_pad_kernel<<<N_BLOCKS, 256>>>(x, out);
}